// round 8
// baseline (speedup 1.0000x reference)
#include <cuda_runtime.h>
#include <math.h>

// Problem constants
#define BATCH 16
#define SEQN  4096
#define DIM   768
#define HEADS 12
#define HD    64
#define TWODIM 1536
#define SCALE 0.125f   // 64^-0.5

// Scratch (device globals: no allocations allowed)
__device__ float g_G[2L * 16 * 768 * 768];    // Gram matrices  X^T X   (75.5 MB)
__device__ float g_P[2L * 16 * 768 * 768];    // P = G @ Wv             (75.5 MB)
__device__ float g_ctx[2L * 16 * 12 * 64 * 64]; // softmaxed contexts   (6.3 MB)

// ---- packed f32x2 helpers (Blackwell FFMA2) ---------------------------------
__device__ __forceinline__ unsigned long long dup2(float f) {
    unsigned long long d;
    asm("mov.b64 %0, {%1, %1};" : "=l"(d) : "r"(__float_as_uint(f)));
    return d;
}
__device__ __forceinline__ void fma2(unsigned long long& d,
                                     unsigned long long a, unsigned long long b) {
    asm("fma.rn.f32x2 %0, %1, %2, %0;" : "+l"(d) : "l"(a), "l"(b));
}
__device__ __forceinline__ float lo32(unsigned long long v) {
    return __uint_as_float((unsigned)(v & 0xffffffffull));
}
__device__ __forceinline__ float hi32(unsigned long long v) {
    return __uint_as_float((unsigned)(v >> 32));
}

// ============================================================================
// Generic C = A^T * B, 128x128 tile, f32 accumulate via FFMA2.
//   C[i][j] = sum_k A[k][i] * B[k][j],  ldC fixed = 768.
// Matrix selection: blockIdx.y = mat = s*16 + b  (s=stream, b=batch).
//   A: if A0 != nullptr: (s ? A1 : A0) + b*sA  else  g_G + mat*768^2
//   B: (s ? B1 : B0) + b*sB
//   C: (cSel ? g_P : g_G) + mat*768^2
// sym: grid.x enumerates tile pairs ti<=tj (21 of them), writes C and C^T.
// ============================================================================
__global__ __launch_bounds__(256, 2)
void gemm_tt_128(const float* __restrict__ A0, const float* __restrict__ A1, long sA, int ldA,
                 const float* __restrict__ B0, const float* __restrict__ B1, long sB, int ldB,
                 int cSel, int K, int sym)
{
    const int mat = blockIdx.y;
    const int s = mat >> 4, b = mat & 15;

    const float* A = A0 ? ((s ? A1 : A0) + (long)b * sA)
                        : (g_G + (long)mat * (768L * 768L));
    const float* Bm = (s ? B1 : B0) + (long)b * sB;
    float* C = (cSel ? g_P : g_G) + (long)mat * (768L * 768L);

    int ti, tj;
    if (sym) {
        int p = blockIdx.x; ti = 0;
        while (p >= 6 - ti) { p -= 6 - ti; ++ti; }
        tj = ti + p;
    } else {
        ti = blockIdx.x / 6; tj = blockIdx.x % 6;
    }
    const int i0 = ti * 128, j0 = tj * 128;

    __shared__ float As[16][128];
    __shared__ float Bs[16][128];

    const int tid = threadIdx.x;
    const int tx = tid & 15, ty = tid >> 4;
    const int kkL = tid >> 5;          // 0..7
    const int cL  = (tid & 31) << 2;   // 0..124

    const float* Ap = A + i0 + (long)kkL * ldA + cL;
    const float* Bp = Bm + j0 + (long)kkL * ldB + cL;

    unsigned long long acc[8][4];
#pragma unroll
    for (int r = 0; r < 8; ++r)
#pragma unroll
        for (int p = 0; p < 4; ++p) acc[r][p] = 0ull;

    // prefetch tile 0 into registers
    float4 ra0 = *(const float4*)(Ap);
    float4 ra1 = *(const float4*)(Ap + 8L * ldA);
    float4 rb0 = *(const float4*)(Bp);
    float4 rb1 = *(const float4*)(Bp + 8L * ldB);

    const int nkt = K >> 4;
    for (int kt = 0; kt < nkt; ++kt) {
        *(float4*)&As[kkL][cL]     = ra0;
        *(float4*)&As[kkL + 8][cL] = ra1;
        *(float4*)&Bs[kkL][cL]     = rb0;
        *(float4*)&Bs[kkL + 8][cL] = rb1;
        __syncthreads();

        if (kt + 1 < nkt) {
            const long ko = (long)(kt + 1) * 16;
            ra0 = *(const float4*)(Ap + ko * ldA);
            ra1 = *(const float4*)(Ap + (ko + 8) * ldA);
            rb0 = *(const float4*)(Bp + ko * ldB);
            rb1 = *(const float4*)(Bp + (ko + 8) * ldB);
        }

#pragma unroll
        for (int kk = 0; kk < 16; ++kk) {
            const float4 a0 = *(const float4*)&As[kk][ty * 4];
            const float4 a1 = *(const float4*)&As[kk][64 + ty * 4];
            const ulonglong2 bq0 = *(const ulonglong2*)&Bs[kk][tx * 4];
            const ulonglong2 bq1 = *(const ulonglong2*)&Bs[kk][64 + tx * 4];
            unsigned long long ap[8];
            ap[0] = dup2(a0.x); ap[1] = dup2(a0.y); ap[2] = dup2(a0.z); ap[3] = dup2(a0.w);
            ap[4] = dup2(a1.x); ap[5] = dup2(a1.y); ap[6] = dup2(a1.z); ap[7] = dup2(a1.w);
            unsigned long long bp[4];
            bp[0] = bq0.x; bp[1] = bq0.y; bp[2] = bq1.x; bp[3] = bq1.y;
#pragma unroll
            for (int r = 0; r < 8; ++r) {
                fma2(acc[r][0], ap[r], bp[0]);
                fma2(acc[r][1], ap[r], bp[1]);
                fma2(acc[r][2], ap[r], bp[2]);
                fma2(acc[r][3], ap[r], bp[3]);
            }
        }
        __syncthreads();
    }

#pragma unroll
    for (int r = 0; r < 8; ++r) {
        const int ii = i0 + ((r < 4) ? (ty * 4 + r) : (64 + ty * 4 + r - 4));
#pragma unroll
        for (int p = 0; p < 4; ++p) {
            const int jj = j0 + ((p < 2) ? (tx * 4 + 2 * p) : (64 + tx * 4 + 2 * (p - 2)));
            const float lo = lo32(acc[r][p]);
            const float hi = hi32(acc[r][p]);
            *(float2*)&C[(long)ii * 768 + jj] = make_float2(lo, hi);
            if (sym && ti != tj) {
                C[(long)jj * 768 + ii]       = lo;
                C[(long)(jj + 1) * 768 + ii] = hi;
            }
        }
    }
}

// ============================================================================
// ctx_h = softmax_over_d( SCALE * Wk_h^T @ P_h ),  one block per (s,b,h).
// Wk_h = W[:, h*64 : h*64+64]  (first 768 cols = K part of the fused KV weight)
// P_h  = P[:, h*64 : h*64+64]
// ============================================================================
__global__ __launch_bounds__(256)
void ctx_softmax_kernel(const float* __restrict__ Wr, const float* __restrict__ Wd)
{
    const int h = blockIdx.x, b = blockIdx.y, s = blockIdx.z;
    const float* Wk = s ? Wd : Wr;
    const float* P  = g_P + (long)(s * 16 + b) * (768L * 768L);

    __shared__ float As[16][64];
    __shared__ float Bs[16][64];
    __shared__ float Ct[64][65];

    const int tid = threadIdx.x;
    const int tx = tid & 15, ty = tid >> 4;
    const int lr = tid >> 4;            // 0..15
    const int lc = (tid & 15) << 2;     // 0..60

    float acc[4][4];
#pragma unroll
    for (int r = 0; r < 4; ++r)
#pragma unroll
        for (int c = 0; c < 4; ++c) acc[r][c] = 0.f;

    for (int kt = 0; kt < 48; ++kt) {
        const long k = (long)kt * 16 + lr;
        *(float4*)&As[lr][lc] = *(const float4*)&Wk[k * TWODIM + h * 64 + lc];
        *(float4*)&Bs[lr][lc] = *(const float4*)&P[k * DIM + h * 64 + lc];
        __syncthreads();
#pragma unroll
        for (int kk = 0; kk < 16; ++kk) {
            float a[4], bb[4];
#pragma unroll
            for (int r = 0; r < 4; ++r) a[r] = As[kk][ty + r * 16];
#pragma unroll
            for (int c = 0; c < 4; ++c) bb[c] = Bs[kk][tx + c * 16];
#pragma unroll
            for (int r = 0; r < 4; ++r)
#pragma unroll
                for (int c = 0; c < 4; ++c) acc[r][c] += a[r] * bb[c];
        }
        __syncthreads();
    }

#pragma unroll
    for (int r = 0; r < 4; ++r)
#pragma unroll
        for (int c = 0; c < 4; ++c)
            Ct[ty + r * 16][tx + c * 16] = acc[r][c] * SCALE;
    __syncthreads();

    if (tid < 64) {
        const int e = tid;
        float m = -3.4e38f;
        for (int d = 0; d < 64; ++d) m = fmaxf(m, Ct[d][e]);
        float sum = 0.f;
        for (int d = 0; d < 64; ++d) {
            const float v = expf(Ct[d][e] - m);
            Ct[d][e] = v;
            sum += v;
        }
        const float inv = 1.f / sum;
        float* dst = g_ctx + (long)((s * 16 + b) * 12 + h) * 4096;
        for (int d = 0; d < 64; ++d) dst[d * 64 + e] = Ct[d][e] * inv;
    }
}

// ============================================================================
// out[s][b][n][h*64+e] = sum_d X_s[b][n][h*64+d] * ctx_{1-s}[b][h][d][e]
// One block: 128 n-rows x 64 e-cols (one head).
// ============================================================================
__global__ __launch_bounds__(256)
void out_kernel(const float* __restrict__ X0, const float* __restrict__ X1,
                float* __restrict__ out)
{
    const int nt = blockIdx.x, h = blockIdx.y;
    const int s = blockIdx.z >> 4, b = blockIdx.z & 15;

    const float* X = (s ? X1 : X0) + (long)b * (SEQN * DIM);
    const float* ctx = g_ctx + (long)(((1 - s) * 16 + b) * 12 + h) * 4096;
    float* O = out + (long)(s * 16 + b) * (SEQN * DIM);
    const int n0 = nt * 128;

    __shared__ float Xs[128][64];
    __shared__ float Cs[64][64];

    const int tid = threadIdx.x;
    const int tx = tid & 15, ty = tid >> 4;
    const int lr = tid >> 4;          // 0..15
    const int lc = (tid & 15) << 2;   // 0..60

#pragma unroll
    for (int l = 0; l < 8; ++l) {
        const int r = lr + l * 16;
        *(float4*)&Xs[r][lc] = *(const float4*)&X[(long)(n0 + r) * DIM + h * 64 + lc];
    }
#pragma unroll
    for (int l = 0; l < 4; ++l) {
        const int r = lr + l * 16;
        *(float4*)&Cs[r][lc] = *(const float4*)&ctx[r * 64 + lc];
    }
    __syncthreads();

    unsigned long long acc[8][2];
#pragma unroll
    for (int r = 0; r < 8; ++r) { acc[r][0] = 0ull; acc[r][1] = 0ull; }

#pragma unroll 4
    for (int kk = 0; kk < 64; ++kk) {
        const ulonglong2 bq = *(const ulonglong2*)&Cs[kk][tx * 4];
        unsigned long long ap[8];
#pragma unroll
        for (int r = 0; r < 8; ++r) {
            const int row = (r < 4) ? (ty * 4 + r) : (64 + ty * 4 + r - 4);
            ap[r] = dup2(Xs[row][kk]);
        }
#pragma unroll
        for (int r = 0; r < 8; ++r) {
            fma2(acc[r][0], ap[r], bq.x);
            fma2(acc[r][1], ap[r], bq.y);
        }
    }

#pragma unroll
    for (int r = 0; r < 8; ++r) {
        const int row = (r < 4) ? (ty * 4 + r) : (64 + ty * 4 + r - 4);
        const long base = (long)(n0 + row) * DIM + h * 64 + tx * 4;
        *(float2*)&O[base]     = make_float2(lo32(acc[r][0]), hi32(acc[r][0]));
        *(float2*)&O[base + 2] = make_float2(lo32(acc[r][1]), hi32(acc[r][1]));
    }
}

// ============================================================================
extern "C" void kernel_launch(void* const* d_in, const int* in_sizes, int n_in,
                              void* d_out, int out_size)
{
    const float* rgb = (const float*)d_in[0];
    const float* dep = (const float*)d_in[1];
    const float* Wr  = (const float*)d_in[2];
    const float* Wd  = (const float*)d_in[3];
    float* out = (float*)d_out;

    const long tokStride = (long)SEQN * DIM;

    // 1) Gram: G[s][b] = X^T X  (symmetric: 21 tile-pairs), K = 4096
    gemm_tt_128<<<dim3(21, 32), 256>>>(rgb, dep, tokStride, DIM,
                                       rgb, dep, tokStride, DIM,
                                       /*cSel=*/0, /*K=*/SEQN, /*sym=*/1);

    // 2) P[s][b] = G @ Wv  (Wv = cols 768..1535 of the fused KV weight), K = 768
    gemm_tt_128<<<dim3(36, 32), 256>>>(nullptr, nullptr, 0, DIM,
                                       Wr + DIM, Wd + DIM, 0, TWODIM,
                                       /*cSel=*/1, /*K=*/DIM, /*sym=*/0);

    // 3) ctx[s][b][h] = softmax_d( SCALE * Wk_h^T @ P_h )
    ctx_softmax_kernel<<<dim3(HEADS, BATCH, 2), 256>>>(Wr, Wd);

    // 4) out[s] = X_s(head-sliced) @ ctx_{1-s}
    out_kernel<<<dim3(SEQN / 128, HEADS, 2 * BATCH), 256>>>(rgb, dep, out);
}

// round 10
// speedup vs baseline: 1.9455x; 1.9455x over previous
#include <cuda_runtime.h>
#include <cuda_bf16.h>
#include <stdint.h>
#include <string.h>
#include <math.h>

// Problem constants
#define BATCH 16
#define SEQN  4096
#define DIM   768
#define HEADS 12
#define HD    64
#define TWODIM 1536
#define SCALE 0.125f   // 64^-0.5

// ---------------------------------------------------------------------------
// Scratch (device globals: no allocations allowed)
// ---------------------------------------------------------------------------
__device__ __nv_bfloat16 g_XhT[2L * 16 * 768 * 4096];   // X^T hi  (201 MB)
__device__ __nv_bfloat16 g_XlT[2L * 16 * 768 * 4096];   // X^T lo  (201 MB)
__device__ __nv_bfloat16 g_Gh [2L * 16 * 768 * 768];    // Gram hi (38 MB)
__device__ __nv_bfloat16 g_Gl [2L * 16 * 768 * 768];    // Gram lo (38 MB)
__device__ __nv_bfloat16 g_WvTh[2L * 768 * 768];        // Wv^T hi
__device__ __nv_bfloat16 g_WvTl[2L * 768 * 768];        // Wv^T lo
__device__ float g_P  [2L * 16 * 768 * 768];            // P = G @ Wv (fp32)
__device__ float g_ctx[2L * 16 * 12 * 64 * 64];         // softmaxed contexts

// ---------------------------------------------------------------------------
// helpers
// ---------------------------------------------------------------------------
__device__ __forceinline__ uint32_t smem_u32(const void* p) {
    uint32_t a;
    asm("{ .reg .u64 t; cvta.to.shared.u64 t, %1; cvt.u32.u64 %0, t; }"
        : "=r"(a) : "l"(p));
    return a;
}

// legacy tensor-core path (baseline PTX, works on plain sm_103 target)
__device__ __forceinline__ void ldsm_x4(uint32_t* r, uint32_t addr) {
    asm volatile("ldmatrix.sync.aligned.m8n8.x4.shared.b16 {%0,%1,%2,%3}, [%4];"
        : "=r"(r[0]), "=r"(r[1]), "=r"(r[2]), "=r"(r[3]) : "r"(addr));
}
__device__ __forceinline__ void mma_bf16(float* c, const uint32_t* a,
                                         uint32_t b0, uint32_t b1) {
    asm volatile(
        "mma.sync.aligned.m16n8k16.row.col.f32.bf16.bf16.f32 "
        "{%0,%1,%2,%3}, {%4,%5,%6,%7}, {%8,%9}, {%0,%1,%2,%3};"
        : "+f"(c[0]), "+f"(c[1]), "+f"(c[2]), "+f"(c[3])
        : "r"(a[0]), "r"(a[1]), "r"(a[2]), "r"(a[3]), "r"(b0), "r"(b1));
}
__device__ __forceinline__ void cpasync16(uint32_t dst, const void* src) {
    asm volatile("cp.async.cg.shared.global [%0], [%1], 16;" :: "r"(dst), "l"(src));
}

// ---- packed f32x2 helpers (Blackwell FFMA2), used by out_kernel ------------
__device__ __forceinline__ unsigned long long dup2(float f) {
    unsigned long long d;
    asm("mov.b64 %0, {%1, %1};" : "=l"(d) : "r"(__float_as_uint(f)));
    return d;
}
__device__ __forceinline__ void fma2(unsigned long long& d,
                                     unsigned long long a, unsigned long long b) {
    asm("fma.rn.f32x2 %0, %1, %2, %0;" : "+l"(d) : "l"(a), "l"(b));
}
__device__ __forceinline__ float lo32(unsigned long long v) {
    return __uint_as_float((unsigned)(v & 0xffffffffull));
}
__device__ __forceinline__ float hi32(unsigned long long v) {
    return __uint_as_float((unsigned)(v >> 32));
}

// bf16 hi/lo split + packing
__device__ __forceinline__ void splitbf(float v, __nv_bfloat16& h, __nv_bfloat16& l) {
    h = __float2bfloat16(v);
    l = __float2bfloat16(v - __bfloat162float(h));
}
__device__ __forceinline__ uint32_t pk2(__nv_bfloat16 a, __nv_bfloat16 b) {
    __nv_bfloat162 t = __halves2bfloat162(a, b);
    uint32_t u; memcpy(&u, &t, 4); return u;
}

// ===========================================================================
// Prep 1: transpose + hi/lo split of X: [mat][4096][768] f32 ->
//         XhT/XlT [mat][768][4096] bf16 (K-major).
// ===========================================================================
__global__ __launch_bounds__(256)
void split_transpose_x(const float* __restrict__ X0, const float* __restrict__ X1)
{
    const int mat = blockIdx.z;
    const int s = mat >> 4, b = mat & 15;
    const float* X = (s ? X1 : X0) + (long)b * SEQN * DIM;
    __nv_bfloat16* Oh = g_XhT + (long)mat * DIM * SEQN;
    __nv_bfloat16* Ol = g_XlT + (long)mat * DIM * SEQN;
    const int n0 = blockIdx.x * 32, c0 = blockIdx.y * 32;

    __shared__ float T[32][33];
    const int tc = threadIdx.x & 31, tr = threadIdx.x >> 5;
#pragma unroll
    for (int k = 0; k < 4; ++k) {
        const int r = tr + k * 8;
        T[r][tc] = X[(long)(n0 + r) * DIM + c0 + tc];
    }
    __syncthreads();
    const int c2 = (threadIdx.x & 15) * 2, rr = threadIdx.x >> 4;
#pragma unroll
    for (int k = 0; k < 2; ++k) {
        const int d = rr + k * 16;
        const float v0 = T[c2][d], v1 = T[c2 + 1][d];
        __nv_bfloat16 h0, l0, h1, l1;
        splitbf(v0, h0, l0); splitbf(v1, h1, l1);
        const long o = (long)(c0 + d) * SEQN + n0 + c2;
        *(uint32_t*)(Oh + o) = pk2(h0, h1);
        *(uint32_t*)(Ol + o) = pk2(l0, l1);
    }
}

// ===========================================================================
// Prep 2: Wv^T hi/lo split:  WvT[s][j][c] = split(W_s[c][768+j])
// ===========================================================================
__global__ __launch_bounds__(256)
void split_weight(const float* __restrict__ Wr, const float* __restrict__ Wd)
{
    const int s = blockIdx.z;
    const float* W = s ? Wd : Wr;
    __nv_bfloat16* Oh = g_WvTh + (long)s * DIM * DIM;
    __nv_bfloat16* Ol = g_WvTl + (long)s * DIM * DIM;
    const int c0 = blockIdx.x * 32, j0 = blockIdx.y * 32;

    __shared__ float T[32][33];
    const int tc = threadIdx.x & 31, tr = threadIdx.x >> 5;
#pragma unroll
    for (int k = 0; k < 4; ++k) {
        const int r = tr + k * 8;
        T[r][tc] = W[(long)(c0 + r) * TWODIM + DIM + j0 + tc];
    }
    __syncthreads();
    const int c2 = (threadIdx.x & 15) * 2, rr = threadIdx.x >> 4;
#pragma unroll
    for (int k = 0; k < 2; ++k) {
        const int j = rr + k * 16;
        const float v0 = T[c2][j], v1 = T[c2 + 1][j];
        __nv_bfloat16 h0, l0, h1, l1;
        splitbf(v0, h0, l0); splitbf(v1, h1, l1);
        const long o = (long)(j0 + j) * DIM + c0 + c2;
        *(uint32_t*)(Oh + o) = pk2(h0, h1);
        *(uint32_t*)(Ol + o) = pk2(l0, l1);
    }
}

// ===========================================================================
// mma.sync split-precision GEMM: D[m][n] = sum_k A[m][k]*B[n][k],
// A = Ah+Al, B = Bh+Bl (bf16 hi/lo): D = AhBh + AhBl + AlBh (drop AlBl).
// Tile 128x128; 8 warps (4x2), warp tile 32x64; K-chunks of 64 in SW128
// SMEM (128B rows), cp.async double-buffered.
// srcSel 0: Gram (A=B=X^T, K=4096, sym -> writes Gh/Gl bf16 + mirror)
// srcSel 1: P    (A=Gram,  B=Wv^T, K=768 -> writes g_P fp32)
// ===========================================================================
#define STAGE 65536
#define SMEM_DYN (2 * STAGE + 1024)

__global__ __launch_bounds__(256, 1)
void mma_gemm_kernel(int srcSel, int sym, int mode)
{
    extern __shared__ char smem_raw[];
    const uint32_t raw = smem_u32(smem_raw);
    const uint32_t sbase = (raw + 1023u) & ~1023u;
    char* sm = smem_raw + (sbase - raw);

    const int tid = threadIdx.x;
    const int lane = tid & 31, wid = tid >> 5;
    const int wm = wid & 3, wn = wid >> 2;
    const int mat = blockIdx.y;

    const __nv_bfloat16 *Ah, *Al, *Bh, *Bl;
    int ldK, K;
    if (srcSel == 0) {
        const long st = (long)DIM * SEQN;
        Ah = g_XhT + mat * st;  Al = g_XlT + mat * st;
        Bh = Ah;                Bl = Al;
        ldK = SEQN; K = SEQN;
    } else {
        const long st = (long)DIM * DIM;
        Ah = g_Gh + mat * st;           Al = g_Gl + mat * st;
        Bh = g_WvTh + (mat >> 4) * st;  Bl = g_WvTl + (mat >> 4) * st;
        ldK = DIM; K = DIM;
    }

    int ti, tj;
    if (sym) {
        int p = blockIdx.x; ti = 0;
        while (p >= 6 - ti) { p -= 6 - ti; ++ti; }
        tj = ti + p;
    } else {
        ti = blockIdx.x / 6; tj = blockIdx.x % 6;
    }
    const int i0 = ti * 128, j0 = tj * 128;
    const bool diag = sym && (ti == tj);
    const int ntiles = diag ? 2 : 4;

    float acc[2][8][4];
#pragma unroll
    for (int mf = 0; mf < 2; ++mf)
#pragma unroll
        for (int nf = 0; nf < 8; ++nf)
#pragma unroll
            for (int q = 0; q < 4; ++q) acc[mf][nf][q] = 0.f;

    // lane-invariant fragment address pieces
    const int amRow0 = wm * 32 + (lane & 15);
    const uint32_t aSel = (uint32_t)((lane >> 4) << 4);
    const int bnRow0 = wn * 64 + (lane & 7) + ((lane >> 4) << 3);
    const uint32_t bSel = (uint32_t)(((lane >> 3) & 1) << 4);

    const int nc = K >> 6;

#define FILL(bufi, cc_) do {                                                   \
    const int kBase_ = (cc_) * 64;                                             \
    _Pragma("unroll")                                                          \
    for (int t = 0; t < 4; ++t) {                                              \
        if (t >= ntiles) break;                                                \
        const __nv_bfloat16* bb = (t == 0) ? Ah : (t == 1) ? Al                \
                                 : (t == 2) ? Bh : Bl;                         \
        const int rb = (t < 2) ? i0 : j0;                                      \
        _Pragma("unroll")                                                      \
        for (int q = 0; q < 4; ++q) {                                          \
            const int u = tid + q * 256;                                       \
            const int r = u >> 3, seg = u & 7;                                 \
            uint32_t off = (uint32_t)(r * 128 + seg * 16);                     \
            off ^= (off >> 3) & 0x70u;                                         \
            cpasync16(sbase + (bufi) * STAGE + t * 16384 + off,                \
                      bb + (long)(rb + r) * ldK + kBase_ + seg * 8);           \
        }                                                                      \
    }                                                                          \
    asm volatile("cp.async.commit_group;" ::: "memory");                       \
} while (0)

    FILL(0, 0);

    for (int c = 0; c < nc; ++c) {
        const int buf = c & 1;
        asm volatile("cp.async.wait_group 0;" ::: "memory");
        __syncthreads();
        if (c + 1 < nc) FILL(buf ^ 1, c + 1);

        const uint32_t sb  = sbase + buf * STAGE;
        const uint32_t bAh = sb, bAl = sb + 16384;
        const uint32_t bBh = diag ? sb : sb + 32768;
        const uint32_t bBl = diag ? (sb + 16384) : (sb + 49152);

#pragma unroll
        for (int ks = 0; ks < 4; ++ks) {
            uint32_t ah[2][4], al[2][4];
#pragma unroll
            for (int mf = 0; mf < 2; ++mf) {
                uint32_t off = (uint32_t)((amRow0 + mf * 16) * 128 + ks * 32) + aSel;
                off ^= (off >> 3) & 0x70u;
                ldsm_x4(ah[mf], bAh + off);
                ldsm_x4(al[mf], bAl + off);
            }
            uint32_t bh[4][4], bl[4][4];
#pragma unroll
            for (int np = 0; np < 4; ++np) {
                uint32_t off = (uint32_t)((bnRow0 + np * 16) * 128 + ks * 32) + bSel;
                off ^= (off >> 3) & 0x70u;
                ldsm_x4(bh[np], bBh + off);
                ldsm_x4(bl[np], bBl + off);
            }
#pragma unroll
            for (int mf = 0; mf < 2; ++mf)
#pragma unroll
                for (int np = 0; np < 4; ++np) {
                    mma_bf16(acc[mf][np * 2],     ah[mf], bh[np][0], bh[np][1]);
                    mma_bf16(acc[mf][np * 2 + 1], ah[mf], bh[np][2], bh[np][3]);
                    mma_bf16(acc[mf][np * 2],     ah[mf], bl[np][0], bl[np][1]);
                    mma_bf16(acc[mf][np * 2 + 1], ah[mf], bl[np][2], bl[np][3]);
                    mma_bf16(acc[mf][np * 2],     al[mf], bh[np][0], bh[np][1]);
                    mma_bf16(acc[mf][np * 2 + 1], al[mf], bh[np][2], bh[np][3]);
                }
        }
        __syncthreads();
    }
#undef FILL

    // ---- epilogue: stage 128x128 fp32 tile in SMEM (pitch 132) ------------
    float* Ct = (float*)sm;
    {
        const int mrow = wm * 32 + (lane >> 2);
        const int ncol = wn * 64 + (lane & 3) * 2;
#pragma unroll
        for (int mf = 0; mf < 2; ++mf)
#pragma unroll
            for (int nf = 0; nf < 8; ++nf) {
                const int r = mrow + mf * 16, cc = ncol + nf * 8;
                Ct[r * 132 + cc]           = acc[mf][nf][0];
                Ct[r * 132 + cc + 1]       = acc[mf][nf][1];
                Ct[(r + 8) * 132 + cc]     = acc[mf][nf][2];
                Ct[(r + 8) * 132 + cc + 1] = acc[mf][nf][3];
            }
    }
    __syncthreads();

    if (mode == 0) {
        __nv_bfloat16* Gh = g_Gh + (long)mat * (768L * 768L);
        __nv_bfloat16* Gl = g_Gl + (long)mat * (768L * 768L);
        for (int idx = tid; idx < 4096; idx += 256) {
            const int r = idx >> 5, cg = (idx & 31) * 4;
            __nv_bfloat16 h[4], l[4];
#pragma unroll
            for (int k = 0; k < 4; ++k)
                splitbf(Ct[r * 132 + cg + k], h[k], l[k]);
            const long o = (long)(i0 + r) * 768 + j0 + cg;
            *(uint2*)(Gh + o) = make_uint2(pk2(h[0], h[1]), pk2(h[2], h[3]));
            *(uint2*)(Gl + o) = make_uint2(pk2(l[0], l[1]), pk2(l[2], l[3]));
        }
        if (sym && ti != tj) {   // mirror tile (transpose), coalesced uint4
            for (int idx = tid; idx < 2048; idx += 256) {
                const int cc = idx >> 4, rg = (idx & 15) * 8;
                uint32_t uh[4], ul[4];
#pragma unroll
                for (int k = 0; k < 4; ++k) {
                    __nv_bfloat16 ha, la, hb, lb;
                    splitbf(Ct[(rg + 2 * k) * 132 + cc], ha, la);
                    splitbf(Ct[(rg + 2 * k + 1) * 132 + cc], hb, lb);
                    uh[k] = pk2(ha, hb); ul[k] = pk2(la, lb);
                }
                const long o = (long)(j0 + cc) * 768 + i0 + rg;
                *(uint4*)(Gh + o) = make_uint4(uh[0], uh[1], uh[2], uh[3]);
                *(uint4*)(Gl + o) = make_uint4(ul[0], ul[1], ul[2], ul[3]);
            }
        }
    } else {
        float* P = g_P + (long)mat * (768L * 768L);
        for (int idx = tid; idx < 4096; idx += 256) {
            const int r = idx >> 5, cg = (idx & 31) * 4;
            *(float4*)&P[(long)(i0 + r) * 768 + j0 + cg] =
                make_float4(Ct[r * 132 + cg], Ct[r * 132 + cg + 1],
                            Ct[r * 132 + cg + 2], Ct[r * 132 + cg + 3]);
        }
    }
}

// ===========================================================================
// ctx_h = softmax_over_d( SCALE * Wk_h^T @ P_h ),  one block per (s,b,h).
// ===========================================================================
__global__ __launch_bounds__(256)
void ctx_softmax_kernel(const float* __restrict__ Wr, const float* __restrict__ Wd)
{
    const int h = blockIdx.x, b = blockIdx.y, s = blockIdx.z;
    const float* Wk = s ? Wd : Wr;
    const float* P  = g_P + (long)(s * 16 + b) * (768L * 768L);

    __shared__ float As[16][64];
    __shared__ float Bs[16][64];
    __shared__ float Ct[64][65];

    const int tid = threadIdx.x;
    const int tx = tid & 15, ty = tid >> 4;
    const int lr = tid >> 4;
    const int lc = (tid & 15) << 2;

    float acc[4][4];
#pragma unroll
    for (int r = 0; r < 4; ++r)
#pragma unroll
        for (int c = 0; c < 4; ++c) acc[r][c] = 0.f;

    for (int kt = 0; kt < 48; ++kt) {
        const long k = (long)kt * 16 + lr;
        *(float4*)&As[lr][lc] = *(const float4*)&Wk[k * TWODIM + h * 64 + lc];
        *(float4*)&Bs[lr][lc] = *(const float4*)&P[k * DIM + h * 64 + lc];
        __syncthreads();
#pragma unroll
        for (int kk = 0; kk < 16; ++kk) {
            float a[4], bb[4];
#pragma unroll
            for (int r = 0; r < 4; ++r) a[r] = As[kk][ty + r * 16];
#pragma unroll
            for (int c = 0; c < 4; ++c) bb[c] = Bs[kk][tx + c * 16];
#pragma unroll
            for (int r = 0; r < 4; ++r)
#pragma unroll
                for (int c = 0; c < 4; ++c) acc[r][c] += a[r] * bb[c];
        }
        __syncthreads();
    }

#pragma unroll
    for (int r = 0; r < 4; ++r)
#pragma unroll
        for (int c = 0; c < 4; ++c)
            Ct[ty + r * 16][tx + c * 16] = acc[r][c] * SCALE;
    __syncthreads();

    if (tid < 64) {
        const int e = tid;
        float m = -3.4e38f;
        for (int d = 0; d < 64; ++d) m = fmaxf(m, Ct[d][e]);
        float sum = 0.f;
        for (int d = 0; d < 64; ++d) {
            const float v = expf(Ct[d][e] - m);
            Ct[d][e] = v;
            sum += v;
        }
        const float inv = 1.f / sum;
        float* dst = g_ctx + (long)((s * 16 + b) * 12 + h) * 4096;
        for (int d = 0; d < 64; ++d) dst[d * 64 + e] = Ct[d][e] * inv;
    }
}

// ===========================================================================
// out[s][b][n][h*64+e] = sum_d X_s[b][n][h*64+d] * ctx_{1-s}[b][h][d][e]
// ===========================================================================
__global__ __launch_bounds__(256)
void out_kernel(const float* __restrict__ X0, const float* __restrict__ X1,
                float* __restrict__ out)
{
    const int nt = blockIdx.x, h = blockIdx.y;
    const int s = blockIdx.z >> 4, b = blockIdx.z & 15;

    const float* X = (s ? X1 : X0) + (long)b * (SEQN * DIM);
    const float* ctx = g_ctx + (long)(((1 - s) * 16 + b) * 12 + h) * 4096;
    float* O = out + (long)(s * 16 + b) * (SEQN * DIM);
    const int n0 = nt * 128;

    __shared__ float Xs[128][64];
    __shared__ float Cs[64][64];

    const int tid = threadIdx.x;
    const int tx = tid & 15, ty = tid >> 4;
    const int lr = tid >> 4;
    const int lc = (tid & 15) << 2;

#pragma unroll
    for (int l = 0; l < 8; ++l) {
        const int r = lr + l * 16;
        *(float4*)&Xs[r][lc] = *(const float4*)&X[(long)(n0 + r) * DIM + h * 64 + lc];
    }
#pragma unroll
    for (int l = 0; l < 4; ++l) {
        const int r = lr + l * 16;
        *(float4*)&Cs[r][lc] = *(const float4*)&ctx[r * 64 + lc];
    }
    __syncthreads();

    unsigned long long acc[8][2];
#pragma unroll
    for (int r = 0; r < 8; ++r) { acc[r][0] = 0ull; acc[r][1] = 0ull; }

#pragma unroll 4
    for (int kk = 0; kk < 64; ++kk) {
        const ulonglong2 bq = *(const ulonglong2*)&Cs[kk][tx * 4];
        unsigned long long ap[8];
#pragma unroll
        for (int r = 0; r < 8; ++r) {
            const int row = (r < 4) ? (ty * 4 + r) : (64 + ty * 4 + r - 4);
            ap[r] = dup2(Xs[row][kk]);
        }
#pragma unroll
        for (int r = 0; r < 8; ++r) {
            fma2(acc[r][0], ap[r], bq.x);
            fma2(acc[r][1], ap[r], bq.y);
        }
    }

#pragma unroll
    for (int r = 0; r < 8; ++r) {
        const int row = (r < 4) ? (ty * 4 + r) : (64 + ty * 4 + r - 4);
        const long base = (long)(n0 + row) * DIM + h * 64 + tx * 4;
        *(float2*)&O[base]     = make_float2(lo32(acc[r][0]), hi32(acc[r][0]));
        *(float2*)&O[base + 2] = make_float2(lo32(acc[r][1]), hi32(acc[r][1]));
    }
}

// ===========================================================================
extern "C" void kernel_launch(void* const* d_in, const int* in_sizes, int n_in,
                              void* d_out, int out_size)
{
    const float* rgb = (const float*)d_in[0];
    const float* dep = (const float*)d_in[1];
    const float* Wr  = (const float*)d_in[2];
    const float* Wd  = (const float*)d_in[3];
    float* out = (float*)d_out;

    cudaFuncSetAttribute(mma_gemm_kernel,
                         cudaFuncAttributeMaxDynamicSharedMemorySize, SMEM_DYN);

    // 0) transpose + hi/lo split of X and Wv
    split_transpose_x<<<dim3(SEQN / 32, DIM / 32, 32), 256>>>(rgb, dep);
    split_weight<<<dim3(DIM / 32, DIM / 32, 2), 256>>>(Wr, Wd);

    // 1) Gram via mma.sync: G = X^T X (split precision, symmetric 21 pairs)
    mma_gemm_kernel<<<dim3(21, 32), 256, SMEM_DYN>>>(0, 1, 0);

    // 2) P = G @ Wv via mma.sync (split precision), fp32 out
    mma_gemm_kernel<<<dim3(36, 32), 256, SMEM_DYN>>>(1, 0, 1);

    // 3) ctx[s][b][h] = softmax_d( SCALE * Wk_h^T @ P_h )
    ctx_softmax_kernel<<<dim3(HEADS, BATCH, 2), 256>>>(Wr, Wd);

    // 4) out[s] = X_s(head-sliced) @ ctx_{1-s}
    out_kernel<<<dim3(SEQN / 128, HEADS, 2 * BATCH), 256>>>(rgb, dep, out);
}

// round 13
// speedup vs baseline: 1.9803x; 1.0179x over previous
#include <cuda_runtime.h>
#include <cuda_fp16.h>
#include <stdint.h>
#include <string.h>
#include <math.h>

// Problem constants
#define BATCH 16
#define SEQN  4096
#define DIM   768
#define HEADS 12
#define HD    64
#define TWODIM 1536
#define SCALE 0.125f   // 64^-0.5

// ---------------------------------------------------------------------------
// Scratch (device globals: no allocations allowed)
// ---------------------------------------------------------------------------
__device__ __half g_XhT[2L * 16 * 768 * 4096];   // X^T hi fp16 (201 MB)
__device__ __half g_Gh [2L * 16 * 768 * 768];    // Gram hi fp16
__device__ __half g_Gl [2L * 16 * 768 * 768];    // Gram lo fp16
__device__ __half g_WvTh[2L * 768 * 768];        // Wv^T hi
__device__ __half g_WvTl[2L * 768 * 768];        // Wv^T lo
__device__ float g_P  [2L * 16 * 768 * 768];     // P = G @ Wv (fp32)
__device__ float g_ctx[2L * 16 * 12 * 64 * 64];  // softmaxed contexts

// ---------------------------------------------------------------------------
// helpers
// ---------------------------------------------------------------------------
__device__ __forceinline__ uint32_t smem_u32(const void* p) {
    uint32_t a;
    asm("{ .reg .u64 t; cvta.to.shared.u64 t, %1; cvt.u32.u64 %0, t; }"
        : "=r"(a) : "l"(p));
    return a;
}

// legacy tensor-core path (baseline PTX, assembles on plain sm_103 target)
__device__ __forceinline__ void ldsm_x4(uint32_t* r, uint32_t addr) {
    asm volatile("ldmatrix.sync.aligned.m8n8.x4.shared.b16 {%0,%1,%2,%3}, [%4];"
        : "=r"(r[0]), "=r"(r[1]), "=r"(r[2]), "=r"(r[3]) : "r"(addr));
}
__device__ __forceinline__ void mma_f16(float* c, const uint32_t* a,
                                        uint32_t b0, uint32_t b1) {
    asm volatile(
        "mma.sync.aligned.m16n8k16.row.col.f32.f16.f16.f32 "
        "{%0,%1,%2,%3}, {%4,%5,%6,%7}, {%8,%9}, {%0,%1,%2,%3};"
        : "+f"(c[0]), "+f"(c[1]), "+f"(c[2]), "+f"(c[3])
        : "r"(a[0]), "r"(a[1]), "r"(a[2]), "r"(a[3]), "r"(b0), "r"(b1));
}
__device__ __forceinline__ void cpasync16(uint32_t dst, const void* src) {
    asm volatile("cp.async.cg.shared.global [%0], [%1], 16;" :: "r"(dst), "l"(src));
}

// ---- packed f32x2 helpers (Blackwell FFMA2), used by out_kernel ------------
__device__ __forceinline__ unsigned long long dup2(float f) {
    unsigned long long d;
    asm("mov.b64 %0, {%1, %1};" : "=l"(d) : "r"(__float_as_uint(f)));
    return d;
}
__device__ __forceinline__ void fma2(unsigned long long& d,
                                     unsigned long long a, unsigned long long b) {
    asm("fma.rn.f32x2 %0, %1, %2, %0;" : "+l"(d) : "l"(a), "l"(b));
}
__device__ __forceinline__ float lo32(unsigned long long v) {
    return __uint_as_float((unsigned)(v & 0xffffffffull));
}
__device__ __forceinline__ float hi32(unsigned long long v) {
    return __uint_as_float((unsigned)(v >> 32));
}

// fp16 hi/lo split + packing
__device__ __forceinline__ void splith(float v, __half& h, __half& l) {
    h = __float2half(v);
    l = __float2half(v - __half2float(h));
}
__device__ __forceinline__ uint32_t pkh2(__half a, __half b) {
    __half2 t = __halves2half2(a, b);
    uint32_t u; memcpy(&u, &t, 4); return u;
}

// ===========================================================================
// Prep 1: transpose X + fp16 hi only: [mat][4096][768] f32 ->
//         XhT [mat][768][4096] fp16 (K-major).
// ===========================================================================
__global__ __launch_bounds__(256)
void split_transpose_x(const float* __restrict__ X0, const float* __restrict__ X1)
{
    const int mat = blockIdx.z;
    const int s = mat >> 4, b = mat & 15;
    const float* X = (s ? X1 : X0) + (long)b * SEQN * DIM;
    __half* Oh = g_XhT + (long)mat * DIM * SEQN;
    const int n0 = blockIdx.x * 32, c0 = blockIdx.y * 32;

    __shared__ float T[32][33];
    const int tc = threadIdx.x & 31, tr = threadIdx.x >> 5;
#pragma unroll
    for (int k = 0; k < 4; ++k) {
        const int r = tr + k * 8;
        T[r][tc] = X[(long)(n0 + r) * DIM + c0 + tc];
    }
    __syncthreads();
    const int c2 = (threadIdx.x & 15) * 2, rr = threadIdx.x >> 4;
#pragma unroll
    for (int k = 0; k < 2; ++k) {
        const int d = rr + k * 16;
        const long o = (long)(c0 + d) * SEQN + n0 + c2;
        *(uint32_t*)(Oh + o) = pkh2(__float2half(T[c2][d]), __float2half(T[c2 + 1][d]));
    }
}

// ===========================================================================
// Prep 2: Wv^T fp16 hi/lo split:  WvT[s][j][c] = split(W_s[c][768+j])
// ===========================================================================
__global__ __launch_bounds__(256)
void split_weight(const float* __restrict__ Wr, const float* __restrict__ Wd)
{
    const int s = blockIdx.z;
    const float* W = s ? Wd : Wr;
    __half* Oh = g_WvTh + (long)s * DIM * DIM;
    __half* Ol = g_WvTl + (long)s * DIM * DIM;
    const int c0 = blockIdx.x * 32, j0 = blockIdx.y * 32;

    __shared__ float T[32][33];
    const int tc = threadIdx.x & 31, tr = threadIdx.x >> 5;
#pragma unroll
    for (int k = 0; k < 4; ++k) {
        const int r = tr + k * 8;
        T[r][tc] = W[(long)(c0 + r) * TWODIM + DIM + j0 + tc];
    }
    __syncthreads();
    const int c2 = (threadIdx.x & 15) * 2, rr = threadIdx.x >> 4;
#pragma unroll
    for (int k = 0; k < 2; ++k) {
        const int j = rr + k * 16;
        __half h0, l0, h1, l1;
        splith(T[c2][j], h0, l0); splith(T[c2 + 1][j], h1, l1);
        const long o = (long)(j0 + j) * DIM + c0 + c2;
        *(uint32_t*)(Oh + o) = pkh2(h0, h1);
        *(uint32_t*)(Ol + o) = pkh2(l0, l1);
    }
}

// ===========================================================================
// mma.sync GEMM: D[m][n] = sum_k A[m][k]*B[n][k]
// srcSel 0 (Gram): single product H^T H, fp16 H = X^T. K=4096, symmetric
//                  tile pairs -> writes Gh/Gl (fp16 hi/lo) + mirror.
// srcSel 1 (P):    3-product split (AhBh+AhBl+AlBh), A=Gram fp16 hi/lo,
//                  B=Wv^T fp16 hi/lo, K=768 -> writes g_P fp32.
// Tile 128x128; 8 warps as 2x4 (warp tile 64x32); K-chunks of 64 in SW128
// SMEM (128B rows), cp.async double-buffered.
// ===========================================================================
#define STAGE 65536
#define SMEM_DYN (2 * STAGE + 1024)

__global__ __launch_bounds__(256, 1)
void mma_gemm_kernel(int srcSel, int sym, int mode)
{
    extern __shared__ char smem_raw[];
    const uint32_t raw = smem_u32(smem_raw);
    const uint32_t sbase = (raw + 1023u) & ~1023u;
    char* sm = smem_raw + (sbase - raw);

    const int tid = threadIdx.x;
    const int lane = tid & 31, wid = tid >> 5;
    const int wm = wid & 1, wn = wid >> 1;
    const int mat = blockIdx.y;

    int ti, tj;
    if (sym) {
        int p = blockIdx.x; ti = 0;
        while (p >= 6 - ti) { p -= 6 - ti; ++ti; }
        tj = ti + p;
    } else {
        ti = blockIdx.x / 6; tj = blockIdx.x % 6;
    }
    const int i0 = ti * 128, j0 = tj * 128;
    const bool diag = sym && (ti == tj);
    const bool tp = (srcSel == 1);          // three-product mode

    // tile fill descriptors
    const __half* tsrc[4];
    int trow[4];
    int ntiles, ldK, K;
    if (srcSel == 0) {
        const __half* Xh = g_XhT + (long)mat * DIM * SEQN;
        tsrc[0] = Xh; trow[0] = i0;
        tsrc[1] = Xh; trow[1] = j0;
        tsrc[2] = Xh; trow[2] = j0;  // unused
        tsrc[3] = Xh; trow[3] = j0;  // unused
        ntiles = diag ? 1 : 2;
        ldK = SEQN; K = SEQN;
    } else {
        const long st = (long)DIM * DIM;
        tsrc[0] = g_Gh + mat * st;           trow[0] = i0;
        tsrc[1] = g_Gl + mat * st;           trow[1] = i0;
        tsrc[2] = g_WvTh + (mat >> 4) * st;  trow[2] = j0;
        tsrc[3] = g_WvTl + (mat >> 4) * st;  trow[3] = j0;
        ntiles = 4;
        ldK = DIM; K = DIM;
    }

    float acc[4][4][4];
#pragma unroll
    for (int mf = 0; mf < 4; ++mf)
#pragma unroll
        for (int nf = 0; nf < 4; ++nf)
#pragma unroll
            for (int q = 0; q < 4; ++q) acc[mf][nf][q] = 0.f;

    // fragment address pieces (warp tile 64x32)
    const int amRow0 = wm * 64 + (lane & 15);
    const uint32_t aSel = (uint32_t)((lane >> 4) << 4);
    const int bnRow0 = wn * 32 + (lane & 7) + ((lane >> 4) << 3);
    const uint32_t bSel = (uint32_t)(((lane >> 3) & 1) << 4);

    const int nc = K >> 6;

#define FILL(bufi, cc_) do {                                                   \
    const int kBase_ = (cc_) * 64;                                             \
    for (int t = 0; t < ntiles; ++t) {                                         \
        const __half* bb = tsrc[t];                                            \
        const int rb = trow[t];                                                \
        _Pragma("unroll")                                                      \
        for (int q = 0; q < 4; ++q) {                                          \
            const int u = tid + q * 256;                                       \
            const int r = u >> 3, seg = u & 7;                                 \
            uint32_t off = (uint32_t)(r * 128 + seg * 16);                     \
            off ^= (off >> 3) & 0x70u;                                         \
            cpasync16(sbase + (bufi) * STAGE + t * 16384 + off,                \
                      bb + (long)(rb + r) * ldK + kBase_ + seg * 8);           \
        }                                                                      \
    }                                                                          \
    asm volatile("cp.async.commit_group;" ::: "memory");                       \
} while (0)

    FILL(0, 0);

    for (int c = 0; c < nc; ++c) {
        const int buf = c & 1;
        asm volatile("cp.async.wait_group 0;" ::: "memory");
        __syncthreads();
        if (c + 1 < nc) FILL(buf ^ 1, c + 1);

        const uint32_t sb  = sbase + buf * STAGE;
        const uint32_t bA  = sb;
        const uint32_t bAl = sb + 16384;
        const uint32_t bB  = tp ? (sb + 32768) : (diag ? sb : sb + 16384);
        const uint32_t bBl = sb + 49152;

#pragma unroll
        for (int ks = 0; ks < 4; ++ks) {
            uint32_t ah[4][4], bhf[2][4];
            uint32_t alf[4][4], blf[2][4];
#pragma unroll
            for (int mf = 0; mf < 4; ++mf) {
                uint32_t off = (uint32_t)((amRow0 + mf * 16) * 128 + ks * 32) + aSel;
                off ^= (off >> 3) & 0x70u;
                ldsm_x4(ah[mf], bA + off);
                if (tp) ldsm_x4(alf[mf], bAl + off);
            }
#pragma unroll
            for (int np = 0; np < 2; ++np) {
                uint32_t off = (uint32_t)((bnRow0 + np * 16) * 128 + ks * 32) + bSel;
                off ^= (off >> 3) & 0x70u;
                ldsm_x4(bhf[np], bB + off);
                if (tp) ldsm_x4(blf[np], bBl + off);
            }
#pragma unroll
            for (int mf = 0; mf < 4; ++mf)
#pragma unroll
                for (int np = 0; np < 2; ++np) {
                    mma_f16(acc[mf][np * 2],     ah[mf], bhf[np][0], bhf[np][1]);
                    mma_f16(acc[mf][np * 2 + 1], ah[mf], bhf[np][2], bhf[np][3]);
                    if (tp) {
                        mma_f16(acc[mf][np * 2],     ah[mf],  blf[np][0], blf[np][1]);
                        mma_f16(acc[mf][np * 2 + 1], ah[mf],  blf[np][2], blf[np][3]);
                        mma_f16(acc[mf][np * 2],     alf[mf], bhf[np][0], bhf[np][1]);
                        mma_f16(acc[mf][np * 2 + 1], alf[mf], bhf[np][2], bhf[np][3]);
                    }
                }
        }
        __syncthreads();
    }
#undef FILL

    // ---- epilogue: stage 128x128 fp32 tile in SMEM (pitch 132) ------------
    float* Ct = (float*)sm;
    {
        const int mrow = wm * 64 + (lane >> 2);
        const int ncol = wn * 32 + (lane & 3) * 2;
#pragma unroll
        for (int mf = 0; mf < 4; ++mf)
#pragma unroll
            for (int nf = 0; nf < 4; ++nf) {
                const int r = mrow + mf * 16, cc = ncol + nf * 8;
                Ct[r * 132 + cc]           = acc[mf][nf][0];
                Ct[r * 132 + cc + 1]       = acc[mf][nf][1];
                Ct[(r + 8) * 132 + cc]     = acc[mf][nf][2];
                Ct[(r + 8) * 132 + cc + 1] = acc[mf][nf][3];
            }
    }
    __syncthreads();

    if (mode == 0) {
        __half* Gh = g_Gh + (long)mat * (768L * 768L);
        __half* Gl = g_Gl + (long)mat * (768L * 768L);
        for (int idx = tid; idx < 4096; idx += 256) {
            const int r = idx >> 5, cg = (idx & 31) * 4;
            __half h[4], l[4];
#pragma unroll
            for (int k = 0; k < 4; ++k)
                splith(Ct[r * 132 + cg + k], h[k], l[k]);
            const long o = (long)(i0 + r) * 768 + j0 + cg;
            *(uint2*)(Gh + o) = make_uint2(pkh2(h[0], h[1]), pkh2(h[2], h[3]));
            *(uint2*)(Gl + o) = make_uint2(pkh2(l[0], l[1]), pkh2(l[2], l[3]));
        }
        if (sym && ti != tj) {   // mirror tile (transpose), coalesced uint4
            for (int idx = tid; idx < 2048; idx += 256) {
                const int cc = idx >> 4, rg = (idx & 15) * 8;
                uint32_t uh[4], ul[4];
#pragma unroll
                for (int k = 0; k < 4; ++k) {
                    __half ha, la, hb, lb;
                    splith(Ct[(rg + 2 * k) * 132 + cc], ha, la);
                    splith(Ct[(rg + 2 * k + 1) * 132 + cc], hb, lb);
                    uh[k] = pkh2(ha, hb); ul[k] = pkh2(la, lb);
                }
                const long o = (long)(j0 + cc) * 768 + i0 + rg;
                *(uint4*)(Gh + o) = make_uint4(uh[0], uh[1], uh[2], uh[3]);
                *(uint4*)(Gl + o) = make_uint4(ul[0], ul[1], ul[2], ul[3]);
            }
        }
    } else {
        float* P = g_P + (long)mat * (768L * 768L);
        for (int idx = tid; idx < 4096; idx += 256) {
            const int r = idx >> 5, cg = (idx & 31) * 4;
            *(float4*)&P[(long)(i0 + r) * 768 + j0 + cg] =
                make_float4(Ct[r * 132 + cg], Ct[r * 132 + cg + 1],
                            Ct[r * 132 + cg + 2], Ct[r * 132 + cg + 3]);
        }
    }
}

// ===========================================================================
// ctx_h = softmax_over_d( SCALE * Wk_h^T @ P_h ),  one block per (s,b,h).
// ===========================================================================
__global__ __launch_bounds__(256)
void ctx_softmax_kernel(const float* __restrict__ Wr, const float* __restrict__ Wd)
{
    const int h = blockIdx.x, b = blockIdx.y, s = blockIdx.z;
    const float* Wk = s ? Wd : Wr;
    const float* P  = g_P + (long)(s * 16 + b) * (768L * 768L);

    __shared__ float As[16][64];
    __shared__ float Bs[16][64];
    __shared__ float Ct[64][65];

    const int tid = threadIdx.x;
    const int tx = tid & 15, ty = tid >> 4;
    const int lr = tid >> 4;
    const int lc = (tid & 15) << 2;

    float acc[4][4];
#pragma unroll
    for (int r = 0; r < 4; ++r)
#pragma unroll
        for (int c = 0; c < 4; ++c) acc[r][c] = 0.f;

    for (int kt = 0; kt < 48; ++kt) {
        const long k = (long)kt * 16 + lr;
        *(float4*)&As[lr][lc] = *(const float4*)&Wk[k * TWODIM + h * 64 + lc];
        *(float4*)&Bs[lr][lc] = *(const float4*)&P[k * DIM + h * 64 + lc];
        __syncthreads();
#pragma unroll
        for (int kk = 0; kk < 16; ++kk) {
            float a[4], bb[4];
#pragma unroll
            for (int r = 0; r < 4; ++r) a[r] = As[kk][ty + r * 16];
#pragma unroll
            for (int c = 0; c < 4; ++c) bb[c] = Bs[kk][tx + c * 16];
#pragma unroll
            for (int r = 0; r < 4; ++r)
#pragma unroll
                for (int c = 0; c < 4; ++c) acc[r][c] += a[r] * bb[c];
        }
        __syncthreads();
    }

#pragma unroll
    for (int r = 0; r < 4; ++r)
#pragma unroll
        for (int c = 0; c < 4; ++c)
            Ct[ty + r * 16][tx + c * 16] = acc[r][c] * SCALE;
    __syncthreads();

    if (tid < 64) {
        const int e = tid;
        float m = -3.4e38f;
        for (int d = 0; d < 64; ++d) m = fmaxf(m, Ct[d][e]);
        float sum = 0.f;
        for (int d = 0; d < 64; ++d) {
            const float v = expf(Ct[d][e] - m);
            Ct[d][e] = v;
            sum += v;
        }
        const float inv = 1.f / sum;
        float* dst = g_ctx + (long)((s * 16 + b) * 12 + h) * 4096;
        for (int d = 0; d < 64; ++d) dst[d * 64 + e] = Ct[d][e] * inv;
    }
}

// ===========================================================================
// out[s][b][n][h*64+e] = sum_d X_s[b][n][h*64+d] * ctx_{1-s}[b][h][d][e]
// ===========================================================================
__global__ __launch_bounds__(256)
void out_kernel(const float* __restrict__ X0, const float* __restrict__ X1,
                float* __restrict__ out)
{
    const int nt = blockIdx.x, h = blockIdx.y;
    const int s = blockIdx.z >> 4, b = blockIdx.z & 15;

    const float* X = (s ? X1 : X0) + (long)b * (SEQN * DIM);
    const float* ctx = g_ctx + (long)(((1 - s) * 16 + b) * 12 + h) * 4096;
    float* O = out + (long)(s * 16 + b) * (SEQN * DIM);
    const int n0 = nt * 128;

    __shared__ float Xs[128][64];
    __shared__ float Cs[64][64];

    const int tid = threadIdx.x;
    const int tx = tid & 15, ty = tid >> 4;
    const int lr = tid >> 4;
    const int lc = (tid & 15) << 2;

#pragma unroll
    for (int l = 0; l < 8; ++l) {
        const int r = lr + l * 16;
        *(float4*)&Xs[r][lc] = *(const float4*)&X[(long)(n0 + r) * DIM + h * 64 + lc];
    }
#pragma unroll
    for (int l = 0; l < 4; ++l) {
        const int r = lr + l * 16;
        *(float4*)&Cs[r][lc] = *(const float4*)&ctx[r * 64 + lc];
    }
    __syncthreads();

    unsigned long long acc[8][2];
#pragma unroll
    for (int r = 0; r < 8; ++r) { acc[r][0] = 0ull; acc[r][1] = 0ull; }

#pragma unroll 4
    for (int kk = 0; kk < 64; ++kk) {
        const ulonglong2 bq = *(const ulonglong2*)&Cs[kk][tx * 4];
        unsigned long long ap[8];
#pragma unroll
        for (int r = 0; r < 8; ++r) {
            const int row = (r < 4) ? (ty * 4 + r) : (64 + ty * 4 + r - 4);
            ap[r] = dup2(Xs[row][kk]);
        }
#pragma unroll
        for (int r = 0; r < 8; ++r) {
            fma2(acc[r][0], ap[r], bq.x);
            fma2(acc[r][1], ap[r], bq.y);
        }
    }

#pragma unroll
    for (int r = 0; r < 8; ++r) {
        const int row = (r < 4) ? (ty * 4 + r) : (64 + ty * 4 + r - 4);
        const long base = (long)(n0 + row) * DIM + h * 64 + tx * 4;
        *(float2*)&O[base]     = make_float2(lo32(acc[r][0]), hi32(acc[r][0]));
        *(float2*)&O[base + 2] = make_float2(lo32(acc[r][1]), hi32(acc[r][1]));
    }
}

// ===========================================================================
extern "C" void kernel_launch(void* const* d_in, const int* in_sizes, int n_in,
                              void* d_out, int out_size)
{
    const float* rgb = (const float*)d_in[0];
    const float* dep = (const float*)d_in[1];
    const float* Wr  = (const float*)d_in[2];
    const float* Wd  = (const float*)d_in[3];
    float* out = (float*)d_out;

    cudaFuncSetAttribute(mma_gemm_kernel,
                         cudaFuncAttributeMaxDynamicSharedMemorySize, SMEM_DYN);

    // 0) transpose X -> fp16 hi (K-major); Wv -> fp16 hi/lo
    split_transpose_x<<<dim3(SEQN / 32, DIM / 32, 32), 256>>>(rgb, dep);
    split_weight<<<dim3(DIM / 32, DIM / 32, 2), 256>>>(Wr, Wd);

    // 1) Gram via mma.sync: G = H^T H (single fp16 product, symmetric pairs)
    mma_gemm_kernel<<<dim3(21, 32), 256, SMEM_DYN>>>(0, 1, 0);

    // 2) P = G @ Wv via mma.sync (fp16 3-product split), fp32 out
    mma_gemm_kernel<<<dim3(36, 32), 256, SMEM_DYN>>>(1, 0, 1);

    // 3) ctx[s][b][h] = softmax_d( SCALE * Wk_h^T @ P_h )
    ctx_softmax_kernel<<<dim3(HEADS, BATCH, 2), 256>>>(Wr, Wd);

    // 4) out[s] = X_s(head-sliced) @ ctx_{1-s}
    out_kernel<<<dim3(SEQN / 128, HEADS, 2 * BATCH), 256>>>(rgb, dep, out);
}

// round 15
// speedup vs baseline: 2.8023x; 1.4151x over previous
#include <cuda_runtime.h>
#include <cuda_fp16.h>
#include <stdint.h>
#include <string.h>
#include <math.h>

// Problem constants
#define BATCH 16
#define SEQN  4096
#define DIM   768
#define HEADS 12
#define HD    64
#define TWODIM 1536
#define SCALE 0.125f   // 64^-0.5

// ---------------------------------------------------------------------------
// Scratch (device globals: no allocations allowed)
// ---------------------------------------------------------------------------
__device__ __half g_XhT[2L * 16 * 768 * 4096];   // X^T fp16 (201 MB)
__device__ __half g_Gh [2L * 16 * 768 * 768];    // Gram hi fp16
__device__ __half g_Gl [2L * 16 * 768 * 768];    // Gram lo fp16
__device__ __half g_WvTh[2L * 768 * 768];        // Wv^T hi
__device__ __half g_WvTl[2L * 768 * 768];        // Wv^T lo
__device__ float g_P  [2L * 16 * 768 * 768];     // P = G @ Wv (fp32)
__device__ float g_ctx[2L * 16 * 12 * 64 * 64];  // softmaxed contexts

// ---------------------------------------------------------------------------
// helpers
// ---------------------------------------------------------------------------
__device__ __forceinline__ uint32_t smem_u32(const void* p) {
    uint32_t a;
    asm("{ .reg .u64 t; cvta.to.shared.u64 t, %1; cvt.u32.u64 %0, t; }"
        : "=r"(a) : "l"(p));
    return a;
}

// legacy tensor-core path (baseline PTX, assembles on plain sm_103 target)
__device__ __forceinline__ void ldsm_x4(uint32_t* r, uint32_t addr) {
    asm volatile("ldmatrix.sync.aligned.m8n8.x4.shared.b16 {%0,%1,%2,%3}, [%4];"
        : "=r"(r[0]), "=r"(r[1]), "=r"(r[2]), "=r"(r[3]) : "r"(addr));
}
__device__ __forceinline__ void mma_f16(float* c, const uint32_t* a,
                                        uint32_t b0, uint32_t b1) {
    asm volatile(
        "mma.sync.aligned.m16n8k16.row.col.f32.f16.f16.f32 "
        "{%0,%1,%2,%3}, {%4,%5,%6,%7}, {%8,%9}, {%0,%1,%2,%3};"
        : "+f"(c[0]), "+f"(c[1]), "+f"(c[2]), "+f"(c[3])
        : "r"(a[0]), "r"(a[1]), "r"(a[2]), "r"(a[3]), "r"(b0), "r"(b1));
}
__device__ __forceinline__ void cpasync16(uint32_t dst, const void* src) {
    asm volatile("cp.async.cg.shared.global [%0], [%1], 16;" :: "r"(dst), "l"(src));
}
#define CP_COMMIT() asm volatile("cp.async.commit_group;" ::: "memory")
#define CP_WAIT1()  asm volatile("cp.async.wait_group 1;" ::: "memory")

// ---- packed f32x2 helpers (Blackwell FFMA2), used by out_kernel ------------
__device__ __forceinline__ unsigned long long dup2(float f) {
    unsigned long long d;
    asm("mov.b64 %0, {%1, %1};" : "=l"(d) : "r"(__float_as_uint(f)));
    return d;
}
__device__ __forceinline__ void fma2(unsigned long long& d,
                                     unsigned long long a, unsigned long long b) {
    asm("fma.rn.f32x2 %0, %1, %2, %0;" : "+l"(d) : "l"(a), "l"(b));
}
__device__ __forceinline__ float lo32(unsigned long long v) {
    return __uint_as_float((unsigned)(v & 0xffffffffull));
}
__device__ __forceinline__ float hi32(unsigned long long v) {
    return __uint_as_float((unsigned)(v >> 32));
}

// fp16 hi/lo split + packing
__device__ __forceinline__ void splith(float v, __half& h, __half& l) {
    h = __float2half(v);
    l = __float2half(v - __half2float(h));
}
__device__ __forceinline__ uint32_t pkh2(__half a, __half b) {
    __half2 t = __halves2half2(a, b);
    uint32_t u; memcpy(&u, &t, 4); return u;
}

// ===========================================================================
// Prep 1: transpose X -> fp16 (K-major): [mat][4096][768] f32 -> [768][4096]
// ===========================================================================
__global__ __launch_bounds__(256)
void split_transpose_x(const float* __restrict__ X0, const float* __restrict__ X1)
{
    const int mat = blockIdx.z;
    const int s = mat >> 4, b = mat & 15;
    const float* X = (s ? X1 : X0) + (long)b * SEQN * DIM;
    __half* Oh = g_XhT + (long)mat * DIM * SEQN;
    const int n0 = blockIdx.x * 32, c0 = blockIdx.y * 32;

    __shared__ float T[32][33];
    const int tc = threadIdx.x & 31, tr = threadIdx.x >> 5;
#pragma unroll
    for (int k = 0; k < 4; ++k) {
        const int r = tr + k * 8;
        T[r][tc] = X[(long)(n0 + r) * DIM + c0 + tc];
    }
    __syncthreads();
    const int c2 = (threadIdx.x & 15) * 2, rr = threadIdx.x >> 4;
#pragma unroll
    for (int k = 0; k < 2; ++k) {
        const int d = rr + k * 16;
        const long o = (long)(c0 + d) * SEQN + n0 + c2;
        *(uint32_t*)(Oh + o) = pkh2(__float2half(T[c2][d]), __float2half(T[c2 + 1][d]));
    }
}

// ===========================================================================
// Prep 2: Wv^T fp16 hi/lo split:  WvT[s][j][c] = split(W_s[c][768+j])
// ===========================================================================
__global__ __launch_bounds__(256)
void split_weight(const float* __restrict__ Wr, const float* __restrict__ Wd)
{
    const int s = blockIdx.z;
    const float* W = s ? Wd : Wr;
    __half* Oh = g_WvTh + (long)s * DIM * DIM;
    __half* Ol = g_WvTl + (long)s * DIM * DIM;
    const int c0 = blockIdx.x * 32, j0 = blockIdx.y * 32;

    __shared__ float T[32][33];
    const int tc = threadIdx.x & 31, tr = threadIdx.x >> 5;
#pragma unroll
    for (int k = 0; k < 4; ++k) {
        const int r = tr + k * 8;
        T[r][tc] = W[(long)(c0 + r) * TWODIM + DIM + j0 + tc];
    }
    __syncthreads();
    const int c2 = (threadIdx.x & 15) * 2, rr = threadIdx.x >> 4;
#pragma unroll
    for (int k = 0; k < 2; ++k) {
        const int j = rr + k * 16;
        __half h0, l0, h1, l1;
        splith(T[c2][j], h0, l0); splith(T[c2 + 1][j], h1, l1);
        const long o = (long)(j0 + j) * DIM + c0 + c2;
        *(uint32_t*)(Oh + o) = pkh2(h0, h1);
        *(uint32_t*)(Ol + o) = pkh2(l0, l1);
    }
}

// ===========================================================================
// mma.sync GEMM, template-specialized:
// TP=0 (Gram): D = H^T H (single fp16 product), K=4096, symmetric tile
//   pairs (21), stage=32KB (2 tiles), 3-stage pipeline, 2 CTAs/SM.
//   Writes Gh/Gl fp16 hi/lo + mirrored tile.
// TP=1 (P):   D = G @ Wv, 3-product fp16 split (AhBh+AhBl+AlBh), K=768,
//   stage=64KB (4 tiles), 3-stage pipeline, 1 CTA/SM. Writes g_P fp32.
// Tile 128x128; 8 warps as 2x4 (warp tile 64x32); SW128 SMEM (128B rows).
// ===========================================================================
#define STG(TP)      ((TP) ? 65536 : 32768)
#define SMEM_DYN(TP) (3 * STG(TP) + 1024)

template<int TP>
__global__ __launch_bounds__(256, TP ? 1 : 2)
void mma_gemm_kernel()
{
    extern __shared__ char smem_raw[];
    const uint32_t raw = smem_u32(smem_raw);
    const uint32_t sbase = (raw + 1023u) & ~1023u;
    char* sm = smem_raw + (sbase - raw);
    const int STB = STG(TP);

    const int tid = threadIdx.x;
    const int lane = tid & 31, wid = tid >> 5;
    const int wm = wid & 1, wn = wid >> 1;
    const int mat = blockIdx.y;

    int ti, tj;
    if (!TP) {
        int p = blockIdx.x; ti = 0;
        while (p >= 6 - ti) { p -= 6 - ti; ++ti; }
        tj = ti + p;
    } else {
        ti = blockIdx.x / 6; tj = blockIdx.x % 6;
    }
    const int i0 = ti * 128, j0 = tj * 128;
    const bool diag = (!TP) && (ti == tj);

    // tile fill descriptors
    const __half* tsrc[4];
    int trow[4];
    int ntiles, ldK, K;
    if (!TP) {
        const __half* Xh = g_XhT + (long)mat * DIM * SEQN;
        tsrc[0] = Xh; trow[0] = i0;
        tsrc[1] = Xh; trow[1] = j0;
        ntiles = diag ? 1 : 2;
        ldK = SEQN; K = SEQN;
    } else {
        const long st = (long)DIM * DIM;
        tsrc[0] = g_Gh + mat * st;           trow[0] = i0;
        tsrc[1] = g_Gl + mat * st;           trow[1] = i0;
        tsrc[2] = g_WvTh + (mat >> 4) * st;  trow[2] = j0;
        tsrc[3] = g_WvTl + (mat >> 4) * st;  trow[3] = j0;
        ntiles = 4;
        ldK = DIM; K = DIM;
    }

    float acc[4][4][4];
#pragma unroll
    for (int mf = 0; mf < 4; ++mf)
#pragma unroll
        for (int nf = 0; nf < 4; ++nf)
#pragma unroll
            for (int q = 0; q < 4; ++q) acc[mf][nf][q] = 0.f;

    // fragment address pieces (warp tile 64x32)
    const int amRow0 = wm * 64 + (lane & 15);
    const uint32_t aSel = (uint32_t)((lane >> 4) << 4);
    const int bnRow0 = wn * 32 + (lane & 7) + ((lane >> 4) << 3);
    const uint32_t bSel = (uint32_t)(((lane >> 3) & 1) << 4);

    const int nc = K >> 6;

#define FILL(st_, cc_) do {                                                    \
    if ((cc_) < nc) {                                                          \
        const int kBase_ = (cc_) * 64;                                         \
        for (int t = 0; t < ntiles; ++t) {                                     \
            const __half* bb = tsrc[t];                                        \
            const int rb = trow[t];                                            \
            _Pragma("unroll")                                                  \
            for (int q = 0; q < 4; ++q) {                                      \
                const int u = tid + q * 256;                                   \
                const int r = u >> 3, seg = u & 7;                             \
                uint32_t off = (uint32_t)(r * 128 + seg * 16);                 \
                off ^= (off >> 3) & 0x70u;                                     \
                cpasync16(sbase + (st_) * STB + t * 16384 + off,               \
                          bb + (long)(rb + r) * ldK + kBase_ + seg * 8);       \
            }                                                                  \
        }                                                                      \
    }                                                                          \
    CP_COMMIT();                                                               \
} while (0)

    FILL(0, 0);
    FILL(1, 1);

    for (int c = 0; c < nc; ++c) {
        CP_WAIT1();            // oldest pending group (fill c) complete
        __syncthreads();       // all warps done computing stage (c+2)%3's old data
        FILL((c + 2) % 3, c + 2);

        const uint32_t sb  = sbase + (c % 3) * STB;
        const uint32_t bA  = sb;
        const uint32_t bAl = sb + 16384;
        const uint32_t bB  = TP ? (sb + 32768) : (diag ? sb : sb + 16384);
        const uint32_t bBl = sb + 49152;

#pragma unroll
        for (int ks = 0; ks < 4; ++ks) {
            uint32_t ah[4][4], bhf[2][4];
            uint32_t alf[4][4], blf[2][4];
#pragma unroll
            for (int mf = 0; mf < 4; ++mf) {
                uint32_t off = (uint32_t)((amRow0 + mf * 16) * 128 + ks * 32) + aSel;
                off ^= (off >> 3) & 0x70u;
                ldsm_x4(ah[mf], bA + off);
                if (TP) ldsm_x4(alf[mf], bAl + off);
            }
#pragma unroll
            for (int np = 0; np < 2; ++np) {
                uint32_t off = (uint32_t)((bnRow0 + np * 16) * 128 + ks * 32) + bSel;
                off ^= (off >> 3) & 0x70u;
                ldsm_x4(bhf[np], bB + off);
                if (TP) ldsm_x4(blf[np], bBl + off);
            }
#pragma unroll
            for (int mf = 0; mf < 4; ++mf)
#pragma unroll
                for (int np = 0; np < 2; ++np) {
                    mma_f16(acc[mf][np * 2],     ah[mf], bhf[np][0], bhf[np][1]);
                    mma_f16(acc[mf][np * 2 + 1], ah[mf], bhf[np][2], bhf[np][3]);
                    if (TP) {
                        mma_f16(acc[mf][np * 2],     ah[mf],  blf[np][0], blf[np][1]);
                        mma_f16(acc[mf][np * 2 + 1], ah[mf],  blf[np][2], blf[np][3]);
                        mma_f16(acc[mf][np * 2],     alf[mf], bhf[np][0], bhf[np][1]);
                        mma_f16(acc[mf][np * 2 + 1], alf[mf], bhf[np][2], bhf[np][3]);
                    }
                }
        }
    }
#undef FILL
    __syncthreads();   // all compute done before reusing stages for epilogue

    // ---- epilogue: stage 128x128 fp32 tile in SMEM (pitch 132) ------------
    float* Ct = (float*)sm;
    {
        const int mrow = wm * 64 + (lane >> 2);
        const int ncol = wn * 32 + (lane & 3) * 2;
#pragma unroll
        for (int mf = 0; mf < 4; ++mf)
#pragma unroll
            for (int nf = 0; nf < 4; ++nf) {
                const int r = mrow + mf * 16, cc = ncol + nf * 8;
                Ct[r * 132 + cc]           = acc[mf][nf][0];
                Ct[r * 132 + cc + 1]       = acc[mf][nf][1];
                Ct[(r + 8) * 132 + cc]     = acc[mf][nf][2];
                Ct[(r + 8) * 132 + cc + 1] = acc[mf][nf][3];
            }
    }
    __syncthreads();

    if (!TP) {
        __half* Gh = g_Gh + (long)mat * (768L * 768L);
        __half* Gl = g_Gl + (long)mat * (768L * 768L);
        for (int idx = tid; idx < 4096; idx += 256) {
            const int r = idx >> 5, cg = (idx & 31) * 4;
            __half h[4], l[4];
#pragma unroll
            for (int k = 0; k < 4; ++k)
                splith(Ct[r * 132 + cg + k], h[k], l[k]);
            const long o = (long)(i0 + r) * 768 + j0 + cg;
            *(uint2*)(Gh + o) = make_uint2(pkh2(h[0], h[1]), pkh2(h[2], h[3]));
            *(uint2*)(Gl + o) = make_uint2(pkh2(l[0], l[1]), pkh2(l[2], l[3]));
        }
        if (ti != tj) {   // mirror tile (transpose), coalesced uint4
            for (int idx = tid; idx < 2048; idx += 256) {
                const int cc = idx >> 4, rg = (idx & 15) * 8;
                uint32_t uh[4], ul[4];
#pragma unroll
                for (int k = 0; k < 4; ++k) {
                    __half ha, la, hb, lb;
                    splith(Ct[(rg + 2 * k) * 132 + cc], ha, la);
                    splith(Ct[(rg + 2 * k + 1) * 132 + cc], hb, lb);
                    uh[k] = pkh2(ha, hb); ul[k] = pkh2(la, lb);
                }
                const long o = (long)(j0 + cc) * 768 + i0 + rg;
                *(uint4*)(Gh + o) = make_uint4(uh[0], uh[1], uh[2], uh[3]);
                *(uint4*)(Gl + o) = make_uint4(ul[0], ul[1], ul[2], ul[3]);
            }
        }
    } else {
        float* P = g_P + (long)mat * (768L * 768L);
        for (int idx = tid; idx < 4096; idx += 256) {
            const int r = idx >> 5, cg = (idx & 31) * 4;
            *(float4*)&P[(long)(i0 + r) * 768 + j0 + cg] =
                make_float4(Ct[r * 132 + cg], Ct[r * 132 + cg + 1],
                            Ct[r * 132 + cg + 2], Ct[r * 132 + cg + 3]);
        }
    }
}

// ===========================================================================
// ctx_h = softmax_over_d( SCALE * Wk_h^T @ P_h ),  one block per (s,b,h).
// ===========================================================================
__global__ __launch_bounds__(256)
void ctx_softmax_kernel(const float* __restrict__ Wr, const float* __restrict__ Wd)
{
    const int h = blockIdx.x, b = blockIdx.y, s = blockIdx.z;
    const float* Wk = s ? Wd : Wr;
    const float* P  = g_P + (long)(s * 16 + b) * (768L * 768L);

    __shared__ float As[16][64];
    __shared__ float Bs[16][64];
    __shared__ float Ct[64][65];

    const int tid = threadIdx.x;
    const int tx = tid & 15, ty = tid >> 4;
    const int lr = tid >> 4;
    const int lc = (tid & 15) << 2;

    float acc[4][4];
#pragma unroll
    for (int r = 0; r < 4; ++r)
#pragma unroll
        for (int c = 0; c < 4; ++c) acc[r][c] = 0.f;

    for (int kt = 0; kt < 48; ++kt) {
        const long k = (long)kt * 16 + lr;
        *(float4*)&As[lr][lc] = *(const float4*)&Wk[k * TWODIM + h * 64 + lc];
        *(float4*)&Bs[lr][lc] = *(const float4*)&P[k * DIM + h * 64 + lc];
        __syncthreads();
#pragma unroll
        for (int kk = 0; kk < 16; ++kk) {
            float a[4], bb[4];
#pragma unroll
            for (int r = 0; r < 4; ++r) a[r] = As[kk][ty + r * 16];
#pragma unroll
            for (int c = 0; c < 4; ++c) bb[c] = Bs[kk][tx + c * 16];
#pragma unroll
            for (int r = 0; r < 4; ++r)
#pragma unroll
                for (int c = 0; c < 4; ++c) acc[r][c] += a[r] * bb[c];
        }
        __syncthreads();
    }

#pragma unroll
    for (int r = 0; r < 4; ++r)
#pragma unroll
        for (int c = 0; c < 4; ++c)
            Ct[ty + r * 16][tx + c * 16] = acc[r][c] * SCALE;
    __syncthreads();

    if (tid < 64) {
        const int e = tid;
        float m = -3.4e38f;
        for (int d = 0; d < 64; ++d) m = fmaxf(m, Ct[d][e]);
        float sum = 0.f;
        for (int d = 0; d < 64; ++d) {
            const float v = expf(Ct[d][e] - m);
            Ct[d][e] = v;
            sum += v;
        }
        const float inv = 1.f / sum;
        float* dst = g_ctx + (long)((s * 16 + b) * 12 + h) * 4096;
        for (int d = 0; d < 64; ++d) dst[d * 64 + e] = Ct[d][e] * inv;
    }
}

// ===========================================================================
// out[s][b][n][h*64+e] = sum_d X_s[b][n][h*64+d] * ctx_{1-s}[b][h][d][e]
// ===========================================================================
__global__ __launch_bounds__(256)
void out_kernel(const float* __restrict__ X0, const float* __restrict__ X1,
                float* __restrict__ out)
{
    const int nt = blockIdx.x, h = blockIdx.y;
    const int s = blockIdx.z >> 4, b = blockIdx.z & 15;

    const float* X = (s ? X1 : X0) + (long)b * (SEQN * DIM);
    const float* ctx = g_ctx + (long)(((1 - s) * 16 + b) * 12 + h) * 4096;
    float* O = out + (long)(s * 16 + b) * (SEQN * DIM);
    const int n0 = nt * 128;

    __shared__ float Xs[128][64];
    __shared__ float Cs[64][64];

    const int tid = threadIdx.x;
    const int tx = tid & 15, ty = tid >> 4;
    const int lr = tid >> 4;
    const int lc = (tid & 15) << 2;

#pragma unroll
    for (int l = 0; l < 8; ++l) {
        const int r = lr + l * 16;
        *(float4*)&Xs[r][lc] = *(const float4*)&X[(long)(n0 + r) * DIM + h * 64 + lc];
    }
#pragma unroll
    for (int l = 0; l < 4; ++l) {
        const int r = lr + l * 16;
        *(float4*)&Cs[r][lc] = *(const float4*)&ctx[r * 64 + lc];
    }
    __syncthreads();

    unsigned long long acc[8][2];
#pragma unroll
    for (int r = 0; r < 8; ++r) { acc[r][0] = 0ull; acc[r][1] = 0ull; }

#pragma unroll 4
    for (int kk = 0; kk < 64; ++kk) {
        const ulonglong2 bq = *(const ulonglong2*)&Cs[kk][tx * 4];
        unsigned long long ap[8];
#pragma unroll
        for (int r = 0; r < 8; ++r) {
            const int row = (r < 4) ? (ty * 4 + r) : (64 + ty * 4 + r - 4);
            ap[r] = dup2(Xs[row][kk]);
        }
#pragma unroll
        for (int r = 0; r < 8; ++r) {
            fma2(acc[r][0], ap[r], bq.x);
            fma2(acc[r][1], ap[r], bq.y);
        }
    }

#pragma unroll
    for (int r = 0; r < 8; ++r) {
        const int row = (r < 4) ? (ty * 4 + r) : (64 + ty * 4 + r - 4);
        const long base = (long)(n0 + row) * DIM + h * 64 + tx * 4;
        *(float2*)&O[base]     = make_float2(lo32(acc[r][0]), hi32(acc[r][0]));
        *(float2*)&O[base + 2] = make_float2(lo32(acc[r][1]), hi32(acc[r][1]));
    }
}

// ===========================================================================
extern "C" void kernel_launch(void* const* d_in, const int* in_sizes, int n_in,
                              void* d_out, int out_size)
{
    const float* rgb = (const float*)d_in[0];
    const float* dep = (const float*)d_in[1];
    const float* Wr  = (const float*)d_in[2];
    const float* Wd  = (const float*)d_in[3];
    float* out = (float*)d_out;

    cudaFuncSetAttribute(mma_gemm_kernel<0>,
                         cudaFuncAttributeMaxDynamicSharedMemorySize, SMEM_DYN(0));
    cudaFuncSetAttribute(mma_gemm_kernel<1>,
                         cudaFuncAttributeMaxDynamicSharedMemorySize, SMEM_DYN(1));

    // 0) transpose X -> fp16 (K-major); Wv -> fp16 hi/lo
    split_transpose_x<<<dim3(SEQN / 32, DIM / 32, 32), 256>>>(rgb, dep);
    split_weight<<<dim3(DIM / 32, DIM / 32, 2), 256>>>(Wr, Wd);

    // 1) Gram: G = H^T H (single fp16 product, symmetric pairs, occ 2)
    mma_gemm_kernel<0><<<dim3(21, 32), 256, SMEM_DYN(0)>>>();

    // 2) P = G @ Wv (fp16 3-product split), fp32 out
    mma_gemm_kernel<1><<<dim3(36, 32), 256, SMEM_DYN(1)>>>();

    // 3) ctx[s][b][h] = softmax_d( SCALE * Wk_h^T @ P_h )
    ctx_softmax_kernel<<<dim3(HEADS, BATCH, 2), 256>>>(Wr, Wd);

    // 4) out[s] = X_s(head-sliced) @ ctx_{1-s}
    out_kernel<<<dim3(SEQN / 128, HEADS, 2 * BATCH), 256>>>(rgb, dep, out);
}